// round 2
// baseline (speedup 1.0000x reference)
#include <cuda_runtime.h>

// Problem constants
#define Nn 8
#define Cc 16
#define Ll 1024
#define Dd 7
#define Hh 16
#define SZ 112      // C*D = H*dh

typedef unsigned long long u64;

// Scratch. Q: [bh][l][8] (pre-scaled by log2(e)/32). K/V duplicated:
// [bh][l][16] = (k0,k0,k1,k1,...,k6,k6,pad,pad) so f32x2 broadcast pairs
// load directly as aligned 64-bit words.
__device__ float4 g_Q [Nn * Hh * Ll * 2];
__device__ float4 g_KD[Nn * Hh * Ll * 4];
__device__ float4 g_VD[Nn * Hh * Ll * 4];

__device__ __forceinline__ float ex2f(float x) {
    float y; asm("ex2.approx.ftz.f32 %0, %1;" : "=f"(y) : "f"(x)); return y;
}
__device__ __forceinline__ u64 pk(float lo, float hi) {
    u64 r; asm("mov.b64 %0, {%1, %2};" : "=l"(r) : "f"(lo), "f"(hi)); return r;
}
__device__ __forceinline__ void upk(float& lo, float& hi, u64 v) {
    asm("mov.b64 {%0, %1}, %2;" : "=f"(lo), "=f"(hi) : "l"(v));
}
__device__ __forceinline__ u64 fma2(u64 a, u64 b, u64 c) {
    u64 d; asm("fma.rn.f32x2 %0, %1, %2, %3;" : "=l"(d) : "l"(a), "l"(b), "l"(c)); return d;
}
__device__ __forceinline__ u64 mul2(u64 a, u64 b) {
    u64 d; asm("mul.rn.f32x2 %0, %1, %2;" : "=l"(d) : "l"(a), "l"(b)); return d;
}
__device__ __forceinline__ u64 add2(u64 a, u64 b) {
    u64 d; asm("add.rn.f32x2 %0, %1, %2;" : "=l"(d) : "l"(a), "l"(b)); return d;
}

// ---------------------------------------------------------------------------
// Projection: q/k/v = xf @ W^T + b. Packed f32x2 inner loop (dim pairs).
// Grid (256 row-blocks of 32, 3 matrices), 128 threads, 64KB smem.
// ---------------------------------------------------------------------------
__global__ __launch_bounds__(128) void proj_kernel(
    const float* __restrict__ x,
    const float* __restrict__ Wq, const float* __restrict__ bq,
    const float* __restrict__ Wk, const float* __restrict__ bk,
    const float* __restrict__ Wv, const float* __restrict__ bv)
{
    extern __shared__ float sm[];
    float* Wt = sm;                    // [112][113]: Wt[i*113+o] = W[o][i]
    float* As = sm + 112 * 113;        // [32][113]
    float* bs = As + 32 * 113;         // [112]

    const int z = blockIdx.y;
    const float* W = (z == 0) ? Wq : ((z == 1) ? Wk : Wv);
    const float* b = (z == 0) ? bq : ((z == 1) ? bk : bv);

    const int tid  = threadIdx.x;
    const int row0 = blockIdx.x * 32;

    for (int e = tid; e < SZ * SZ; e += 128) {
        int o = e / SZ, i = e - o * SZ;
        Wt[i * 113 + o] = W[e];
    }
    for (int e = tid; e < 32 * SZ; e += 128) {
        int r = e / SZ, i = e - r * SZ;
        int row = row0 + r;
        int n = row >> 10, l = row & 1023;
        int c = i / Dd, dd = i - c * Dd;
        As[r * 113 + i] = x[(((n * Cc + c) << 10) + l) * Dd + dd];
    }
    if (tid < SZ) bs[tid] = b[tid];
    __syncthreads();

    const int rr = tid >> 4;   // 4 rows: rr*4 .. rr*4+3
    const int oc = tid & 15;   // head 0..15 -> outputs oc*7..oc*7+6

    // Accumulators initialized with bias (dim-pair packed).
    u64 acc2[4][4];
    {
        u64 b0 = pk(bs[oc * 7 + 0], bs[oc * 7 + 1]);
        u64 b1 = pk(bs[oc * 7 + 2], bs[oc * 7 + 3]);
        u64 b2 = pk(bs[oc * 7 + 4], bs[oc * 7 + 5]);
        u64 b3 = pk(bs[oc * 7 + 6], 0.0f);
#pragma unroll
        for (int k = 0; k < 4; ++k) {
            acc2[k][0] = b0; acc2[k][1] = b1; acc2[k][2] = b2; acc2[k][3] = b3;
        }
    }

#pragma unroll 4
    for (int i = 0; i < SZ; ++i) {
        const float* wr = &Wt[i * 113 + oc * 7];
        u64 w2[4];
        w2[0] = pk(wr[0], wr[1]);
        w2[1] = pk(wr[2], wr[3]);
        w2[2] = pk(wr[4], wr[5]);
        w2[3] = pk(wr[6], 0.0f);
#pragma unroll
        for (int k = 0; k < 4; ++k) {
            float a = As[(rr * 4 + k) * 113 + i];
            u64 a2 = pk(a, a);
#pragma unroll
            for (int j = 0; j < 4; ++j)
                acc2[k][j] = fma2(a2, w2[j], acc2[k][j]);
        }
    }

    const float qscale = 1.4426950408889634f / 32.0f;  // log2(e)/sqrt(L)
#pragma unroll
    for (int k = 0; k < 4; ++k) {
        int row = row0 + rr * 4 + k;
        int n = row >> 10, l = row & 1023;
        int bh = n * Hh + oc;
        float r0, r1, r2, r3, r4, r5, r6, r7;
        upk(r0, r1, acc2[k][0]);
        upk(r2, r3, acc2[k][1]);
        upk(r4, r5, acc2[k][2]);
        upk(r6, r7, acc2[k][3]);
        if (z == 0) {
            float4* p = g_Q + (bh * Ll + l) * 2;
            p[0] = make_float4(r0 * qscale, r1 * qscale, r2 * qscale, r3 * qscale);
            p[1] = make_float4(r4 * qscale, r5 * qscale, r6 * qscale, 0.0f);
        } else {
            float4* p = ((z == 1) ? g_KD : g_VD) + (bh * Ll + l) * 4;
            p[0] = make_float4(r0, r0, r1, r1);
            p[1] = make_float4(r2, r2, r3, r3);
            p[2] = make_float4(r4, r4, r5, r5);
            p[3] = make_float4(r6, r6, 0.0f, 0.0f);
        }
    }
}

// ---------------------------------------------------------------------------
// Fused attention with packed f32x2 math. One CTA per (n,h); duplicated
// K and V (64KB each) in SMEM. 256 threads, 4 query rows per thread packed
// as 2 row-pairs. Per thread-key: 14 FFMA2 (QK) + 14 FFMA2 (AV) + 2 ADD2
// + 4 MUFU + 8 broadcast LDS.128. No pack MOVs in the loop except the e-pair.
// ---------------------------------------------------------------------------
__global__ __launch_bounds__(256) void attn_kernel(float* __restrict__ out)
{
    extern __shared__ float sm[];
    float4* sK = (float4*)sm;          // 4096 float4 = 64KB
    float4* sV = sK + 4096;            // 4096 float4 = 64KB

    const int bh  = blockIdx.x;
    const int tid = threadIdx.x;

    const float4* gK = g_KD + bh * (Ll * 4);
    const float4* gV = g_VD + bh * (Ll * 4);
    for (int e = tid; e < 4096; e += 256) {
        sK[e] = gK[e];
        sV[e] = gV[e];
    }

    // Row-pair packed Q: q2[p][j] = (q[2p][j], q[2p+1][j]), rows tid+256*k.
    u64 q2[2][7];
#pragma unroll
    for (int p = 0; p < 2; ++p) {
        const float* qa = (const float*)(g_Q + (bh * Ll + tid + 256 * (2 * p + 0)) * 2);
        const float* qb = (const float*)(g_Q + (bh * Ll + tid + 256 * (2 * p + 1)) * 2);
#pragma unroll
        for (int j = 0; j < 7; ++j) q2[p][j] = pk(qa[j], qb[j]);
    }
    __syncthreads();

    const ulonglong2* Kp = (const ulonglong2*)sm;   // 4096 (4 per key)
    const ulonglong2* Vp = Kp + 4096;

    u64 ssum2[2] = {0ull, 0ull};
    u64 acc2[2][7];
#pragma unroll
    for (int p = 0; p < 2; ++p)
#pragma unroll
        for (int j = 0; j < 7; ++j) acc2[p][j] = 0ull;

#pragma unroll 2
    for (int jj = 0; jj < Ll; ++jj) {
        ulonglong2 ka = Kp[4 * jj + 0];   // (k0k0, k1k1)
        ulonglong2 kb = Kp[4 * jj + 1];   // (k2k2, k3k3)
        ulonglong2 kc = Kp[4 * jj + 2];   // (k4k4, k5k5)
        ulonglong2 kd = Kp[4 * jj + 3];   // (k6k6, --)
        ulonglong2 va = Vp[4 * jj + 0];
        ulonglong2 vb = Vp[4 * jj + 1];
        ulonglong2 vc = Vp[4 * jj + 2];
        ulonglong2 vd = Vp[4 * jj + 3];
#pragma unroll
        for (int p = 0; p < 2; ++p) {
            u64 s = mul2(q2[p][0], ka.x);
            s = fma2(q2[p][1], ka.y, s);
            s = fma2(q2[p][2], kb.x, s);
            s = fma2(q2[p][3], kb.y, s);
            s = fma2(q2[p][4], kc.x, s);
            s = fma2(q2[p][5], kc.y, s);
            s = fma2(q2[p][6], kd.x, s);
            float sl, sh;
            upk(sl, sh, s);
            u64 e2 = pk(ex2f(sl), ex2f(sh));
            ssum2[p] = add2(ssum2[p], e2);
            acc2[p][0] = fma2(e2, va.x, acc2[p][0]);
            acc2[p][1] = fma2(e2, va.y, acc2[p][1]);
            acc2[p][2] = fma2(e2, vb.x, acc2[p][2]);
            acc2[p][3] = fma2(e2, vb.y, acc2[p][3]);
            acc2[p][4] = fma2(e2, vc.x, acc2[p][4]);
            acc2[p][5] = fma2(e2, vc.y, acc2[p][5]);
            acc2[p][6] = fma2(e2, vd.x, acc2[p][6]);
        }
    }

    float s0, s1, s2, s3;
    upk(s0, s1, ssum2[0]);
    upk(s2, s3, ssum2[1]);
    float inv[4] = {1.0f / s0, 1.0f / s1, 1.0f / s2, 1.0f / s3};

#pragma unroll
    for (int p = 0; p < 2; ++p) {
        float* po0 = out + (bh * Ll + tid + 256 * (2 * p + 0)) * Dd;
        float* po1 = out + (bh * Ll + tid + 256 * (2 * p + 1)) * Dd;
#pragma unroll
        for (int j = 0; j < 7; ++j) {
            float lo, hi;
            upk(lo, hi, acc2[p][j]);
            po0[j] = lo * inv[2 * p + 0];
            po1[j] = hi * inv[2 * p + 1];
        }
    }
}

extern "C" void kernel_launch(void* const* d_in, const int* in_sizes, int n_in,
                              void* d_out, int out_size)
{
    const float* x  = (const float*)d_in[0];
    const float* Wq = (const float*)d_in[1];
    const float* bq = (const float*)d_in[2];
    const float* Wk = (const float*)d_in[3];
    const float* bk = (const float*)d_in[4];
    const float* Wv = (const float*)d_in[5];
    const float* bv = (const float*)d_in[6];

    cudaFuncSetAttribute(proj_kernel, cudaFuncAttributeMaxDynamicSharedMemorySize, 65536);
    cudaFuncSetAttribute(attn_kernel, cudaFuncAttributeMaxDynamicSharedMemorySize, 131072);

    proj_kernel<<<dim3(256, 3, 1), 128, 65536>>>(x, Wq, bq, Wk, bk, Wv, bv);
    attn_kernel<<<Nn * Hh, 256, 131072>>>((float*)d_out);
}